// round 7
// baseline (speedup 1.0000x reference)
#include <cuda_runtime.h>
#include <cstdint>

#define Bz 4
#define Tz 1024
#define Dz 1024
#define Hz 16
#define DHz 64
#define Mz (Bz*Tz)        // 4096
#define Nz Dz
#define MD (Mz*Dz)        // 4,194,304
#define NBH (Bz*Hz)       // 64
#define CL 64             // chunk length
#define NC (Tz/CL)        // 16 chunks

__device__ float g_bufR[MD], g_bufK[MD], g_bufV[MD], g_bufE[MD], g_bufO[MD];
__device__ float g_acat[Mz * 2048];               // [x, x_prev] tf32, 32MB
__device__ float g_wcat[4096 * 2048];             // stacked scaled weights, 32MB
__device__ float g_wro[Dz * Dz];                  // W_o tf32
__device__ float g_state[NBH * NC * DHz * DHz];   // chunk states
__device__ float g_wprod[NBH * NC * DHz];         // per-chunk decay products
__device__ float g_bsum[Bz * Tz * Hz];            // bonus coefficients

__device__ __forceinline__ float to_tf32(float x)
{
    uint32_t d;
    asm("cvt.rna.tf32.f32 %0, %1;" : "=r"(d) : "f"(x));
    return __uint_as_float(d);
}
__device__ __forceinline__ uint32_t smem_to_u32(const void* p) {
    uint32_t a;
    asm("{ .reg .u64 t; cvta.to.shared.u64 t, %1; cvt.u32.u64 %0, t; }"
        : "=r"(a) : "l"(p));
    return a;
}
__device__ __forceinline__ void cp16(uint32_t dst, const void* src) {
    asm volatile("cp.async.cg.shared.global [%0], [%1], 16;"
                 :: "r"(dst), "l"(src));
}
__device__ __forceinline__ void cp_commit() {
    asm volatile("cp.async.commit_group;" ::: "memory");
}
__device__ __forceinline__ void mma_tf32(float c[4], const uint32_t a[4],
                                         const uint32_t b[2])
{
    asm volatile(
        "mma.sync.aligned.m16n8k8.row.col.f32.tf32.tf32.f32 "
        "{%0,%1,%2,%3}, {%4,%5,%6,%7}, {%8,%9}, {%0,%1,%2,%3};"
        : "+f"(c[0]), "+f"(c[1]), "+f"(c[2]), "+f"(c[3])
        : "r"(a[0]), "r"(a[1]), "r"(a[2]), "r"(a[3]),
          "r"(b[0]), "r"(b[1]));
}

// ---------------------------------------------------------------------------
// weight prep: Wcat[n][k] = W_which[ncol][k<1024?k:k-1024] * (tm or 1-tm),
// tf32-rounded; plus W_o rounding. float4-granular.
// ---------------------------------------------------------------------------
__global__ void __launch_bounds__(256) wprep_kernel(
    const float4* __restrict__ Wr, const float4* __restrict__ Wk,
    const float4* __restrict__ Wv, const float4* __restrict__ Ww,
    const float4* __restrict__ Wo,
    const float* __restrict__ tmr, const float* __restrict__ tmk,
    const float* __restrict__ tmv, const float* __restrict__ tmw)
{
    int idx = blockIdx.x * 256 + threadIdx.x;
    if (idx < 2097152) {                 // 4096*2048/4
        int n  = idx >> 9;
        int kc = idx & 511;
        int which = n >> 10;
        int ncol  = n & 1023;
        const float4* Wsrc = which == 0 ? Wr : which == 1 ? Wk
                           : which == 2 ? Wv : Ww;
        const float* tm = which == 0 ? tmr : which == 1 ? tmk
                        : which == 2 ? tmv : tmw;
        int k = kc << 2;
        float4 v, t;
        if (k < 1024) {
            v = Wsrc[(ncol << 8) + kc];
            t.x = tm[k]; t.y = tm[k+1]; t.z = tm[k+2]; t.w = tm[k+3];
        } else {
            int k2 = k - 1024;
            v = Wsrc[(ncol << 8) + (k2 >> 2)];
            t.x = 1.f - tm[k2];     t.y = 1.f - tm[k2 + 1];
            t.z = 1.f - tm[k2 + 2]; t.w = 1.f - tm[k2 + 3];
        }
        v.x = to_tf32(v.x * t.x); v.y = to_tf32(v.y * t.y);
        v.z = to_tf32(v.z * t.z); v.w = to_tf32(v.w * t.w);
        reinterpret_cast<float4*>(g_wcat)[idx] = v;
    } else {
        int j = idx - 2097152;           // 0..262143
        float4 v = Wo[j];
        v.x = to_tf32(v.x); v.y = to_tf32(v.y);
        v.z = to_tf32(v.z); v.w = to_tf32(v.w);
        reinterpret_cast<float4*>(g_wro)[j] = v;
    }
}

// ---------------------------------------------------------------------------
// Acat[m][k] = k<1024 ? tf32(x[m][k]) : (t>0 ? tf32(x[m-1][k-1024]) : 0)
// ---------------------------------------------------------------------------
__global__ void __launch_bounds__(256) acat_kernel(const float4* __restrict__ x)
{
    int idx = blockIdx.x * 256 + threadIdx.x;   // 2M float4
    int m  = idx >> 9;
    int kc = idx & 511;
    int k  = kc << 2;
    int t  = m & (Tz - 1);
    float4 v = make_float4(0.f, 0.f, 0.f, 0.f);
    if (k < 1024) v = x[(m << 8) + kc];
    else if (t != 0) v = x[((m - 1) << 8) + ((k - 1024) >> 2)];
    v.x = to_tf32(v.x); v.y = to_tf32(v.y);
    v.z = to_tf32(v.z); v.w = to_tf32(v.w);
    reinterpret_cast<float4*>(g_acat)[idx] = v;
}

// ---------------------------------------------------------------------------
// tf32 mma.sync GEMM: C[m][col] = sum_k A[m][k]*W[n][k], tile 128x128, BK=32,
// 8 warps (2m x 4n), warp tile 64x32, cp.async double buffer, 2 CTAs/SM.
// ---------------------------------------------------------------------------
#define GSLD 36
#define TBUF (128 * GSLD)                    // floats per tile buffer
#define GSMB (4 * TBUF * 4)                  // 73728 bytes

__device__ __forceinline__ void gemm_body(
    const float* __restrict__ A, int lda,
    const float* __restrict__ W, int ldw,
    float* __restrict__ C, int ldc, int cbase,
    int K, int epi)
{
    extern __shared__ __align__(16) float sm[];
    float* As = sm;                  // [2][TBUF]
    float* Bs = sm + 2 * TBUF;       // [2][TBUF]
    uint32_t a32 = smem_to_u32(As);
    uint32_t b32 = smem_to_u32(Bs);

    int tid  = threadIdx.x;
    int lane = tid & 31;
    int wid  = tid >> 5;
    int bm = blockIdx.y * 128;
    int bn = blockIdx.x * 128;

    int wm = (wid >> 2) * 64;
    int wn = (wid & 3) * 32;
    int frow = lane >> 2;
    int fk   = lane & 3;

    float acc[4][4][4];
    #pragma unroll
    for (int i = 0; i < 4; i++)
        #pragma unroll
        for (int j = 0; j < 4; j++)
            #pragma unroll
            for (int r = 0; r < 4; r++) acc[i][j][r] = 0.f;

    #define GSTAGE(CC, BUF)                                                  \
    {                                                                        \
        const char* ap = (const char*)(A + (size_t)bm * lda + (CC) * 32);    \
        const char* bp = (const char*)(W + (size_t)bn * ldw + (CC) * 32);    \
        _Pragma("unroll")                                                    \
        for (int i = 0; i < 4; i++) {                                        \
            int g = i * 256 + tid;                                           \
            int r = g >> 3;                                                  \
            int gc = (g & 7) << 4;                                           \
            cp16(a32 + (BUF) * (TBUF * 4) + r * (GSLD * 4) + gc,             \
                 ap + (size_t)r * (lda * 4) + gc);                           \
            cp16(b32 + (BUF) * (TBUF * 4) + r * (GSLD * 4) + gc,             \
                 bp + (size_t)r * (ldw * 4) + gc);                           \
        }                                                                    \
    }

    GSTAGE(0, 0)
    cp_commit();

    int NIT = K >> 5;
    for (int c = 0; c < NIT; c++) {
        int buf = c & 1;
        if (c + 1 < NIT) {
            GSTAGE(c + 1, buf ^ 1)
            cp_commit();
            asm volatile("cp.async.wait_group 1;" ::: "memory");
        } else {
            asm volatile("cp.async.wait_group 0;" ::: "memory");
        }
        __syncthreads();

        const float* a_s = As + buf * TBUF;
        const float* b_s = Bs + buf * TBUF;
        #pragma unroll
        for (int ks = 0; ks < 4; ks++) {
            int ko = ks * 8;
            uint32_t afr[4][4], bfr[4][2];
            #pragma unroll
            for (int mt = 0; mt < 4; mt++) {
                const float* p = &a_s[(wm + mt * 16 + frow) * GSLD + ko + fk];
                afr[mt][0] = __float_as_uint(p[0]);
                afr[mt][1] = __float_as_uint(p[8 * GSLD]);
                afr[mt][2] = __float_as_uint(p[4]);
                afr[mt][3] = __float_as_uint(p[8 * GSLD + 4]);
            }
            #pragma unroll
            for (int nt = 0; nt < 4; nt++) {
                const float* q = &b_s[(wn + nt * 8 + frow) * GSLD + ko + fk];
                bfr[nt][0] = __float_as_uint(q[0]);
                bfr[nt][1] = __float_as_uint(q[4]);
            }
            #pragma unroll
            for (int mt = 0; mt < 4; mt++)
                #pragma unroll
                for (int nt = 0; nt < 4; nt++)
                    mma_tf32(acc[mt][nt], afr[mt], bfr[nt]);
        }
        __syncthreads();
    }
    #undef GSTAGE

    #pragma unroll
    for (int mt = 0; mt < 4; mt++) {
        int row = bm + wm + mt * 16 + frow;
        #pragma unroll
        for (int nt = 0; nt < 4; nt++) {
            int col = cbase + wn + nt * 8 + fk * 2;
            float vv[4];
            #pragma unroll
            for (int r = 0; r < 4; r++) {
                float v = acc[mt][nt][r];
                if (epi == 1)      v = 1.f / (1.f + __expf(-v));
                else if (epi == 2) v = 0.999900004999833f / (1.f + __expf(-v));
                vv[r] = v;
            }
            *(float2*)&C[(size_t)row * ldc + col]       = make_float2(vv[0], vv[1]);
            *(float2*)&C[(size_t)(row + 8) * ldc + col] = make_float2(vv[2], vv[3]);
        }
    }
}

__global__ void __launch_bounds__(256, 2) proj_gemm()
{
    int bn = blockIdx.x * 128;
    int which = bn >> 10;
    float* dst = which == 0 ? g_bufR : which == 1 ? g_bufK
               : which == 2 ? g_bufV : g_bufE;
    int epi = (which == 0) ? 1 : (which == 3) ? 2 : 0;
    gemm_body(g_acat, 2048, g_wcat, 2048, dst, 1024, bn & 1023, 2048, epi);
}

__global__ void __launch_bounds__(256, 2) out_gemm(float* __restrict__ out)
{
    gemm_body(g_bufO, 1024, g_wro, 1024, out, 1024, blockIdx.x * 128, 1024, 0);
}

// ---------------------------------------------------------------------------
// bonus coefficients: g_bsum[b,t,h] = sum_i r[i] * exp(u[i]+k[i])
// ---------------------------------------------------------------------------
__global__ void __launch_bounds__(256) bonus_kernel(const float* __restrict__ u)
{
    int warp = (blockIdx.x * blockDim.x + threadIdx.x) >> 5;
    int lane = threadIdx.x & 31;
    if (warp >= Bz * Tz * Hz) return;
    int bt = warp / Hz;
    int h  = warp - bt * Hz;

    int base = bt * Dz + h * 64;
    float r0 = g_bufR[base + lane];
    float r1 = g_bufR[base + 32 + lane];
    float k0 = g_bufK[base + lane];
    float k1 = g_bufK[base + 32 + lane];
    float u0 = u[h * 64 + lane];
    float u1 = u[h * 64 + 32 + lane];

    float term = r0 * __expf(u0 + k0) + r1 * __expf(u1 + k1);
    #pragma unroll
    for (int off = 16; off > 0; off >>= 1)
        term += __shfl_xor_sync(0xffffffffu, term, off);
    if (lane == 0) g_bsum[warp] = term;
}

// ---------------------------------------------------------------------------
// Pass A: chunk-local scan, zero init. grid (NC-1, NBH), 128 threads.
// ---------------------------------------------------------------------------
__global__ void __launch_bounds__(128) scanA_kernel()
{
    extern __shared__ __align__(16) float sm[];
    float* k_s = sm;
    float* e_s = sm + 4096;
    float* v_s = sm + 8192;

    int tid  = threadIdx.x;
    int j    = tid & 63;
    int half = tid >> 6;
    int c  = blockIdx.x;
    int bh = blockIdx.y;
    int b = bh >> 4, h = bh & 15;

    int base0 = (b * Tz + c * CL) * Dz + h * 64;

    #pragma unroll
    for (int it = 0; it < 8; it++) {
        int f  = it * 128 + tid;
        int t  = f >> 4;
        int i4 = (f & 15) << 2;
        int ga = base0 + t * Dz + i4;
        int sa = t * 64 + i4;
        *(float4*)&k_s[sa] = *(const float4*)&g_bufK[ga];
        *(float4*)&e_s[sa] = *(const float4*)&g_bufE[ga];
        *(float4*)&v_s[sa] = *(const float4*)&g_bufV[ga];
    }
    __syncthreads();

    float s[32];
    #pragma unroll
    for (int i = 0; i < 32; i++) s[i] = 0.f;

    for (int t = 0; t < CL; t++) {
        float vj = v_s[t * 64 + j];
        const float4* kp = (const float4*)&k_s[t * 64 + half * 32];
        const float4* ep = (const float4*)&e_s[t * 64 + half * 32];
        #pragma unroll
        for (int q = 0; q < 8; q++) {
            float4 kv = kp[q], ev = ep[q];
            s[q * 4 + 0] = ev.x * s[q * 4 + 0] + kv.x * vj;
            s[q * 4 + 1] = ev.y * s[q * 4 + 1] + kv.y * vj;
            s[q * 4 + 2] = ev.z * s[q * 4 + 2] + kv.z * vj;
            s[q * 4 + 3] = ev.w * s[q * 4 + 3] + kv.w * vj;
        }
    }

    int slot = (bh * NC + c) * DHz;
    #pragma unroll 8
    for (int ii = 0; ii < 32; ii++)
        g_state[(size_t)(slot + half * 32 + ii) * DHz + j] = s[ii];

    if (half == 0) {
        float w0 = 1.f, w1 = 1.f, w2 = 1.f, w3 = 1.f;
        #pragma unroll
        for (int t = 0; t < CL; t += 4) {
            w0 *= e_s[(t + 0) * 64 + j];
            w1 *= e_s[(t + 1) * 64 + j];
            w2 *= e_s[(t + 2) * 64 + j];
            w3 *= e_s[(t + 3) * 64 + j];
        }
        g_wprod[slot + j] = (w0 * w1) * (w2 * w3);
    }
}

// ---------------------------------------------------------------------------
// Pass B: sequential prefix over chunks. grid NBH, 128 threads (i-split).
// ---------------------------------------------------------------------------
__global__ void __launch_bounds__(128) scanB_kernel()
{
    __shared__ float s_w[64];
    int tid  = threadIdx.x;
    int j    = tid & 63;
    int half = tid >> 6;
    int bh = blockIdx.x;

    float R[32];
    #pragma unroll
    for (int i = 0; i < 32; i++) R[i] = 0.f;

    for (int c = 0; c < NC; c++) {
        int slot = (bh * NC + c) * DHz;
        if (c < NC - 1) {
            if (tid < 64) s_w[tid] = g_wprod[slot + tid];
            __syncthreads();
            #pragma unroll 8
            for (int ii = 0; ii < 32; ii++) {
                int i = half * 32 + ii;
                size_t a = (size_t)(slot + i) * DHz + j;
                float local = g_state[a];
                g_state[a] = R[ii];
                R[ii] = s_w[i] * R[ii] + local;
            }
            __syncthreads();
        } else {
            #pragma unroll 8
            for (int ii = 0; ii < 32; ii++)
                g_state[(size_t)(slot + half * 32 + ii) * DHz + j] = R[ii];
        }
    }
}

// ---------------------------------------------------------------------------
// Pass C: outputs. grid (NC, NBH), 128 threads, no per-step barriers.
// ---------------------------------------------------------------------------
__global__ void __launch_bounds__(128) scanC_kernel()
{
    extern __shared__ __align__(16) float sm[];
    float* k_s = sm;
    float* e_s = sm + 4096;
    float* v_s = sm + 8192;
    float* r_s = sm + 12288;
    float* op  = sm + 16384;
    float* bs_s = sm + 24576;

    int tid  = threadIdx.x;
    int j    = tid & 63;
    int half = tid >> 6;
    int c  = blockIdx.x;
    int bh = blockIdx.y;
    int b = bh >> 4, h = bh & 15;

    int base0 = (b * Tz + c * CL) * Dz + h * 64;
    int bbase = (b * Tz + c * CL) * Hz + h;

    #pragma unroll
    for (int it = 0; it < 8; it++) {
        int f  = it * 128 + tid;
        int t  = f >> 4;
        int i4 = (f & 15) << 2;
        int ga = base0 + t * Dz + i4;
        int sa = t * 64 + i4;
        *(float4*)&k_s[sa] = *(const float4*)&g_bufK[ga];
        *(float4*)&e_s[sa] = *(const float4*)&g_bufE[ga];
        *(float4*)&v_s[sa] = *(const float4*)&g_bufV[ga];
        *(float4*)&r_s[sa] = *(const float4*)&g_bufR[ga];
    }
    if (tid < 64) bs_s[tid] = g_bsum[bbase + tid * Hz];

    float s[32];
    {
        int slot = (bh * NC + c) * DHz;
        #pragma unroll 8
        for (int ii = 0; ii < 32; ii++)
            s[ii] = g_state[(size_t)(slot + half * 32 + ii) * DHz + j];
    }
    __syncthreads();

    float* myop = op + half * 4096;
    for (int t = 0; t < CL; t++) {
        float vj = v_s[t * 64 + j];
        const float4* rp = (const float4*)&r_s[t * 64 + half * 32];
        const float4* kp = (const float4*)&k_s[t * 64 + half * 32];
        const float4* ep = (const float4*)&e_s[t * 64 + half * 32];
        float o0 = 0.f, o1 = 0.f, o2 = 0.f, o3 = 0.f;
        #pragma unroll
        for (int q = 0; q < 8; q++) {
            float4 rv = rp[q], kv = kp[q], ev = ep[q];
            o0 += rv.x * s[q * 4 + 0]; s[q * 4 + 0] = ev.x * s[q * 4 + 0] + kv.x * vj;
            o1 += rv.y * s[q * 4 + 1]; s[q * 4 + 1] = ev.y * s[q * 4 + 1] + kv.y * vj;
            o2 += rv.z * s[q * 4 + 2]; s[q * 4 + 2] = ev.z * s[q * 4 + 2] + kv.z * vj;
            o3 += rv.w * s[q * 4 + 3]; s[q * 4 + 3] = ev.w * s[q * 4 + 3] + kv.w * vj;
        }
        myop[t * 64 + j] = ((o0 + o1) + (o2 + o3));
    }
    __syncthreads();

    #pragma unroll
    for (int it = 0; it < 32; it++) {
        int f  = it * 128 + tid;
        int t  = f >> 6;
        int jj = f & 63;
        float o = op[f] + op[4096 + f] + bs_s[t] * v_s[f];
        g_bufO[base0 + t * Dz + jj] = o;
    }
}

// ---------------------------------------------------------------------------
// GroupNorm + r-multiply; outputs tf32-rounded (feeds final GEMM only)
// ---------------------------------------------------------------------------
__global__ void __launch_bounds__(256) gnorm_kernel(const float* __restrict__ ln_w,
                                                    const float* __restrict__ ln_b)
{
    int warp = (blockIdx.x * blockDim.x + threadIdx.x) >> 5;
    int lane = threadIdx.x & 31;
    if (warp >= Bz * Tz * Hz) return;

    int base = warp * 64;
    float a0 = g_bufO[base + lane];
    float a1 = g_bufO[base + 32 + lane];

    float sum = a0 + a1;
    float sq  = a0 * a0 + a1 * a1;
    #pragma unroll
    for (int off = 16; off > 0; off >>= 1) {
        sum += __shfl_xor_sync(0xffffffffu, sum, off);
        sq  += __shfl_xor_sync(0xffffffffu, sq,  off);
    }
    float mean = sum * (1.f / 64.f);
    float var  = sq * (1.f / 64.f) - mean * mean;
    float rs   = rsqrtf(var + 1e-5f);

    float r0 = g_bufR[base + lane];
    float r1 = g_bufR[base + 32 + lane];
    g_bufO[base + lane] =
        to_tf32(((a0 - mean) * rs * ln_w[lane] + ln_b[lane]) * r0);
    g_bufO[base + 32 + lane] =
        to_tf32(((a1 - mean) * rs * ln_w[lane + 32] + ln_b[lane + 32]) * r1);
}

// ---------------------------------------------------------------------------
extern "C" void kernel_launch(void* const* d_in, const int* in_sizes, int n_in,
                              void* d_out, int out_size)
{
    const float* x    = (const float*)d_in[0];
    const float* W_r  = (const float*)d_in[1];
    const float* W_k  = (const float*)d_in[2];
    const float* W_v  = (const float*)d_in[3];
    const float* W_w  = (const float*)d_in[4];
    const float* W_o  = (const float*)d_in[5];
    const float* u    = (const float*)d_in[6];
    const float* tm_r = (const float*)d_in[7];
    const float* tm_k = (const float*)d_in[8];
    const float* tm_v = (const float*)d_in[9];
    const float* tm_w = (const float*)d_in[10];
    const float* ln_w = (const float*)d_in[11];
    const float* ln_b = (const float*)d_in[12];
    float* out = (float*)d_out;

    cudaFuncSetAttribute(scanA_kernel,
        cudaFuncAttributeMaxDynamicSharedMemorySize, 12288 * 4);
    cudaFuncSetAttribute(scanC_kernel,
        cudaFuncAttributeMaxDynamicSharedMemorySize, 24640 * 4);
    cudaFuncSetAttribute(proj_gemm,
        cudaFuncAttributeMaxDynamicSharedMemorySize, GSMB);
    cudaFuncSetAttribute(out_gemm,
        cudaFuncAttributeMaxDynamicSharedMemorySize, GSMB);

    wprep_kernel<<<9216, 256>>>(
        (const float4*)W_r, (const float4*)W_k, (const float4*)W_v,
        (const float4*)W_w, (const float4*)W_o,
        tm_r, tm_k, tm_v, tm_w);

    acat_kernel<<<8192, 256>>>((const float4*)x);

    proj_gemm<<<dim3(4096 / 128, Mz / 128), 256, GSMB>>>();

    bonus_kernel<<<(Bz * Tz * Hz) / 8, 256>>>(u);

    scanA_kernel<<<dim3(NC - 1, NBH), 128, 12288 * 4>>>();
    scanB_kernel<<<NBH, 128>>>();
    scanC_kernel<<<dim3(NC, NBH), 128, 24640 * 4>>>();

    gnorm_kernel<<<(Bz * Tz * Hz) / 8, 256>>>(ln_w, ln_b);

    out_gemm<<<dim3(Nz / 128, Mz / 128), 256, GSMB>>>(out);
}

// round 8
// speedup vs baseline: 1.3530x; 1.3530x over previous
#include <cuda_runtime.h>
#include <cstdint>

#define Bz 4
#define Tz 1024
#define Dz 1024
#define Hz 16
#define DHz 64
#define Mz (Bz*Tz)        // 4096
#define Kz Dz
#define Nz Dz
#define MD (Mz*Dz)        // 4,194,304
#define NBH (Bz*Hz)       // 64
#define CL 64             // chunk length
#define NC (Tz/CL)        // 16 chunks

// scratch: 0..3 = xr,xk,xv,xw (tf32-rounded) ; 4=r ; 5=k ; 6=v ; 7=exp(w) ; 8=o
__device__ float g_buf[9][MD];
__device__ float g_wr[5 * Dz * Dz];               // tf32-rounded weights
__device__ float g_state[NBH * NC * DHz * DHz];   // chunk states
__device__ float g_wprod[NBH * NC * DHz];         // per-chunk decay products
__device__ float g_bsum[Bz * Tz * Hz];            // bonus coefficients

__device__ __forceinline__ float to_tf32(float x)
{
    uint32_t d;
    asm("cvt.rna.tf32.f32 %0, %1;" : "=r"(d) : "f"(x));
    return __uint_as_float(d);
}
__device__ __forceinline__ uint32_t smem_to_u32(const void* p) {
    uint32_t a;
    asm("{ .reg .u64 t; cvta.to.shared.u64 t, %1; cvt.u32.u64 %0, t; }"
        : "=r"(a) : "l"(p));
    return a;
}
__device__ __forceinline__ void cp16(uint32_t dst, const void* src) {
    asm volatile("cp.async.cg.shared.global [%0], [%1], 16;"
                 :: "r"(dst), "l"(src));
}
__device__ __forceinline__ void cp_commit() {
    asm volatile("cp.async.commit_group;" ::: "memory");
}
__device__ __forceinline__ void mma_tf32(float c[4], const uint32_t a[4],
                                         const uint32_t b[2])
{
    asm volatile(
        "mma.sync.aligned.m16n8k8.row.col.f32.tf32.tf32.f32 "
        "{%0,%1,%2,%3}, {%4,%5,%6,%7}, {%8,%9}, {%0,%1,%2,%3};"
        : "+f"(c[0]), "+f"(c[1]), "+f"(c[2]), "+f"(c[3])
        : "r"(a[0]), "r"(a[1]), "r"(a[2]), "r"(a[3]),
          "r"(b[0]), "r"(b[1]));
}

// ---------------------------------------------------------------------------
// round the 5 weight matrices to tf32 into g_wr
// ---------------------------------------------------------------------------
__global__ void __launch_bounds__(256) roundw_kernel(
    const float4* __restrict__ a, const float4* __restrict__ b,
    const float4* __restrict__ c, const float4* __restrict__ d,
    const float4* __restrict__ e)
{
    int idx = blockIdx.x * 256 + threadIdx.x;
    int which = idx >> 18;
    int off = idx & 262143;
    const float4* src = which == 0 ? a : which == 1 ? b : which == 2 ? c
                       : which == 3 ? d : e;
    float4 v = src[off];
    v.x = to_tf32(v.x); v.y = to_tf32(v.y); v.z = to_tf32(v.z); v.w = to_tf32(v.w);
    reinterpret_cast<float4*>(g_wr)[idx] = v;
}

// ---------------------------------------------------------------------------
// token-shift mix, outputs tf32-rounded (GEMM inputs only)
// ---------------------------------------------------------------------------
__global__ void __launch_bounds__(256) mix_kernel(
    const float4* __restrict__ x,
    const float4* __restrict__ tmr, const float4* __restrict__ tmk,
    const float4* __restrict__ tmv, const float4* __restrict__ tmw)
{
    int idx = blockIdx.x * blockDim.x + threadIdx.x;
    int m  = idx >> 8;
    int c4 = idx & 255;
    int t  = m & (Tz - 1);

    float4 xc = x[idx];
    float4 xp = make_float4(0.f, 0.f, 0.f, 0.f);
    if (t != 0) xp = x[idx - 256];

    float4 w, o;
    #define DO_MIX(TMV, DSTI)                                   \
        w = TMV[c4];                                            \
        o.x = to_tf32(w.x * xc.x + (1.f - w.x) * xp.x);         \
        o.y = to_tf32(w.y * xc.y + (1.f - w.y) * xp.y);         \
        o.z = to_tf32(w.z * xc.z + (1.f - w.z) * xp.z);         \
        o.w = to_tf32(w.w * xc.w + (1.f - w.w) * xp.w);         \
        reinterpret_cast<float4*>(g_buf[DSTI])[idx] = o;
    DO_MIX(tmr, 0)
    DO_MIX(tmk, 1)
    DO_MIX(tmv, 2)
    DO_MIX(tmw, 3)
    #undef DO_MIX
}

// ---------------------------------------------------------------------------
// tf32 mma.sync GEMM: C[m][n] = sum_k A[m][k]*W[n][k]
// CTA tile 128x128, BK=32, 4 warps (2m x 2n), warp tile 64x64 (8 MAC/LDS-byte)
// cp.async double buffer, 2 CTAs/SM. epi: 0 id, 1 sigmoid, 2 sigmoid*e^-1e-4
// ---------------------------------------------------------------------------
#define GSLD 36
#define TBUF (128 * GSLD)                    // floats per tile buffer
#define GSMB (4 * TBUF * 4)                  // 73728 bytes

__device__ __forceinline__ void gemm_body(
    const float* __restrict__ A,
    const float* __restrict__ W,
    float* __restrict__ C, int epi)
{
    extern __shared__ __align__(16) float sm[];
    float* As = sm;                  // [2][TBUF]
    float* Bs = sm + 2 * TBUF;       // [2][TBUF]
    uint32_t a32 = smem_to_u32(As);
    uint32_t b32 = smem_to_u32(Bs);

    int tid  = threadIdx.x;          // 0..127
    int lane = tid & 31;
    int wid  = tid >> 5;             // 0..3
    int bm = blockIdx.y * 128;
    int bn = blockIdx.x * 128;

    int wm = (wid >> 1) * 64;        // 0 / 64
    int wn = (wid & 1) * 64;         // 0 / 64
    int frow = lane >> 2;
    int fk   = lane & 3;

    float acc[4][8][4];
    #pragma unroll
    for (int i = 0; i < 4; i++)
        #pragma unroll
        for (int j = 0; j < 8; j++)
            #pragma unroll
            for (int r = 0; r < 4; r++) acc[i][j][r] = 0.f;

    // staging: 128 rows x 8 granules(16B) per matrix, 128 threads -> 8 each
    #define GSTAGE(CC, BUF)                                                  \
    {                                                                        \
        const char* ap = (const char*)(A + (size_t)bm * Kz + (CC) * 32);     \
        const char* bp = (const char*)(W + (size_t)bn * Kz + (CC) * 32);     \
        _Pragma("unroll")                                                    \
        for (int i = 0; i < 8; i++) {                                        \
            int g = i * 128 + tid;                                           \
            int r = g >> 3;                                                  \
            int gc = (g & 7) << 4;                                           \
            cp16(a32 + (BUF) * (TBUF * 4) + r * (GSLD * 4) + gc,             \
                 ap + (size_t)r * (Kz * 4) + gc);                            \
            cp16(b32 + (BUF) * (TBUF * 4) + r * (GSLD * 4) + gc,             \
                 bp + (size_t)r * (Kz * 4) + gc);                            \
        }                                                                    \
    }

    GSTAGE(0, 0)
    cp_commit();

    const int NIT = Kz >> 5;         // 32
    for (int c = 0; c < NIT; c++) {
        int buf = c & 1;
        if (c + 1 < NIT) {
            GSTAGE(c + 1, buf ^ 1)
            cp_commit();
            asm volatile("cp.async.wait_group 1;" ::: "memory");
        } else {
            asm volatile("cp.async.wait_group 0;" ::: "memory");
        }
        __syncthreads();

        const float* a_s = As + buf * TBUF;
        const float* b_s = Bs + buf * TBUF;
        #pragma unroll
        for (int ks = 0; ks < 4; ks++) {
            int ko = ks * 8;
            uint32_t afr[4][4], bfr[8][2];
            #pragma unroll
            for (int mt = 0; mt < 4; mt++) {
                const float* p = &a_s[(wm + mt * 16 + frow) * GSLD + ko + fk];
                afr[mt][0] = __float_as_uint(p[0]);
                afr[mt][1] = __float_as_uint(p[8 * GSLD]);
                afr[mt][2] = __float_as_uint(p[4]);
                afr[mt][3] = __float_as_uint(p[8 * GSLD + 4]);
            }
            #pragma unroll
            for (int nt = 0; nt < 8; nt++) {
                const float* q = &b_s[(wn + nt * 8 + frow) * GSLD + ko + fk];
                bfr[nt][0] = __float_as_uint(q[0]);
                bfr[nt][1] = __float_as_uint(q[4]);
            }
            #pragma unroll
            for (int mt = 0; mt < 4; mt++)
                #pragma unroll
                for (int nt = 0; nt < 8; nt++)
                    mma_tf32(acc[mt][nt], afr[mt], bfr[nt]);
        }
        __syncthreads();
    }
    #undef GSTAGE

    #pragma unroll
    for (int mt = 0; mt < 4; mt++) {
        int row = bm + wm + mt * 16 + frow;
        #pragma unroll
        for (int nt = 0; nt < 8; nt++) {
            int col = bn + wn + nt * 8 + fk * 2;
            float vv[4];
            #pragma unroll
            for (int r = 0; r < 4; r++) {
                float v = acc[mt][nt][r];
                if (epi == 1)      v = 1.f / (1.f + __expf(-v));
                else if (epi == 2) v = 0.999900004999833f / (1.f + __expf(-v));
                vv[r] = v;
            }
            *(float2*)&C[(size_t)row * Nz + col]       = make_float2(vv[0], vv[1]);
            *(float2*)&C[(size_t)(row + 8) * Nz + col] = make_float2(vv[2], vv[3]);
        }
    }
}

__global__ void __launch_bounds__(128, 2) proj_gemm()
{
    int which = blockIdx.z;
    int epi = (which == 0) ? 1 : (which == 3) ? 2 : 0;
    gemm_body(g_buf[which], g_wr + (size_t)which * (Dz * Dz),
              g_buf[4 + which], epi);
}

__global__ void __launch_bounds__(128, 2) out_gemm(float* __restrict__ out)
{
    gemm_body(g_buf[8], g_wr + (size_t)4 * (Dz * Dz), out, 0);
}

// ---------------------------------------------------------------------------
// bonus coefficients: g_bsum[b,t,h] = sum_i r[i] * exp(u[i]+k[i])
// ---------------------------------------------------------------------------
__global__ void __launch_bounds__(256) bonus_kernel(const float* __restrict__ u)
{
    int warp = (blockIdx.x * blockDim.x + threadIdx.x) >> 5;
    int lane = threadIdx.x & 31;
    if (warp >= Bz * Tz * Hz) return;
    int bt = warp / Hz;
    int h  = warp - bt * Hz;

    int base = bt * Dz + h * 64;
    float r0 = g_buf[4][base + lane];
    float r1 = g_buf[4][base + 32 + lane];
    float k0 = g_buf[5][base + lane];
    float k1 = g_buf[5][base + 32 + lane];
    float u0 = u[h * 64 + lane];
    float u1 = u[h * 64 + 32 + lane];

    float term = r0 * __expf(u0 + k0) + r1 * __expf(u1 + k1);
    #pragma unroll
    for (int off = 16; off > 0; off >>= 1)
        term += __shfl_xor_sync(0xffffffffu, term, off);
    if (lane == 0) g_bsum[warp] = term;
}

// ---------------------------------------------------------------------------
// Pass A: chunk-local scan, zero init. grid (NC-1, NBH), 128 threads.
// ---------------------------------------------------------------------------
__global__ void __launch_bounds__(128) scanA_kernel()
{
    extern __shared__ __align__(16) float sm[];
    float* k_s = sm;
    float* e_s = sm + 4096;
    float* v_s = sm + 8192;

    int tid  = threadIdx.x;
    int j    = tid & 63;
    int half = tid >> 6;
    int c  = blockIdx.x;
    int bh = blockIdx.y;
    int b = bh >> 4, h = bh & 15;

    int base0 = (b * Tz + c * CL) * Dz + h * 64;

    #pragma unroll
    for (int it = 0; it < 8; it++) {
        int f  = it * 128 + tid;
        int t  = f >> 4;
        int i4 = (f & 15) << 2;
        int ga = base0 + t * Dz + i4;
        int sa = t * 64 + i4;
        *(float4*)&k_s[sa] = *(const float4*)&g_buf[5][ga];
        *(float4*)&e_s[sa] = *(const float4*)&g_buf[7][ga];
        *(float4*)&v_s[sa] = *(const float4*)&g_buf[6][ga];
    }
    __syncthreads();

    float s[32];
    #pragma unroll
    for (int i = 0; i < 32; i++) s[i] = 0.f;

    for (int t = 0; t < CL; t++) {
        float vj = v_s[t * 64 + j];
        const float4* kp = (const float4*)&k_s[t * 64 + half * 32];
        const float4* ep = (const float4*)&e_s[t * 64 + half * 32];
        #pragma unroll
        for (int q = 0; q < 8; q++) {
            float4 kv = kp[q], ev = ep[q];
            s[q * 4 + 0] = ev.x * s[q * 4 + 0] + kv.x * vj;
            s[q * 4 + 1] = ev.y * s[q * 4 + 1] + kv.y * vj;
            s[q * 4 + 2] = ev.z * s[q * 4 + 2] + kv.z * vj;
            s[q * 4 + 3] = ev.w * s[q * 4 + 3] + kv.w * vj;
        }
    }

    int slot = (bh * NC + c) * DHz;
    #pragma unroll 8
    for (int ii = 0; ii < 32; ii++)
        g_state[(size_t)(slot + half * 32 + ii) * DHz + j] = s[ii];

    if (half == 0) {
        float w0 = 1.f, w1 = 1.f, w2 = 1.f, w3 = 1.f;
        #pragma unroll
        for (int t = 0; t < CL; t += 4) {
            w0 *= e_s[(t + 0) * 64 + j];
            w1 *= e_s[(t + 1) * 64 + j];
            w2 *= e_s[(t + 2) * 64 + j];
            w3 *= e_s[(t + 3) * 64 + j];
        }
        g_wprod[slot + j] = (w0 * w1) * (w2 * w3);
    }
}

// ---------------------------------------------------------------------------
// Pass B: sequential prefix over chunks. grid NBH, 128 threads (i-split).
// ---------------------------------------------------------------------------
__global__ void __launch_bounds__(128) scanB_kernel()
{
    __shared__ float s_w[64];
    int tid  = threadIdx.x;
    int j    = tid & 63;
    int half = tid >> 6;
    int bh = blockIdx.x;

    float R[32];
    #pragma unroll
    for (int i = 0; i < 32; i++) R[i] = 0.f;

    for (int c = 0; c < NC; c++) {
        int slot = (bh * NC + c) * DHz;
        if (c < NC - 1) {
            if (tid < 64) s_w[tid] = g_wprod[slot + tid];
            __syncthreads();
            #pragma unroll 8
            for (int ii = 0; ii < 32; ii++) {
                int i = half * 32 + ii;
                size_t a = (size_t)(slot + i) * DHz + j;
                float local = g_state[a];
                g_state[a] = R[ii];
                R[ii] = s_w[i] * R[ii] + local;
            }
            __syncthreads();
        } else {
            #pragma unroll 8
            for (int ii = 0; ii < 32; ii++)
                g_state[(size_t)(slot + half * 32 + ii) * DHz + j] = R[ii];
        }
    }
}

// ---------------------------------------------------------------------------
// Pass C: outputs. grid (NC, NBH), 128 threads, no per-step barriers.
// ---------------------------------------------------------------------------
__global__ void __launch_bounds__(128) scanC_kernel()
{
    extern __shared__ __align__(16) float sm[];
    float* k_s = sm;
    float* e_s = sm + 4096;
    float* v_s = sm + 8192;
    float* r_s = sm + 12288;
    float* op  = sm + 16384;
    float* bs_s = sm + 24576;

    int tid  = threadIdx.x;
    int j    = tid & 63;
    int half = tid >> 6;
    int c  = blockIdx.x;
    int bh = blockIdx.y;
    int b = bh >> 4, h = bh & 15;

    int base0 = (b * Tz + c * CL) * Dz + h * 64;
    int bbase = (b * Tz + c * CL) * Hz + h;

    #pragma unroll
    for (int it = 0; it < 8; it++) {
        int f  = it * 128 + tid;
        int t  = f >> 4;
        int i4 = (f & 15) << 2;
        int ga = base0 + t * Dz + i4;
        int sa = t * 64 + i4;
        *(float4*)&k_s[sa] = *(const float4*)&g_buf[5][ga];
        *(float4*)&e_s[sa] = *(const float4*)&g_buf[7][ga];
        *(float4*)&v_s[sa] = *(const float4*)&g_buf[6][ga];
        *(float4*)&r_s[sa] = *(const float4*)&g_buf[4][ga];
    }
    if (tid < 64) bs_s[tid] = g_bsum[bbase + tid * Hz];

    float s[32];
    {
        int slot = (bh * NC + c) * DHz;
        #pragma unroll 8
        for (int ii = 0; ii < 32; ii++)
            s[ii] = g_state[(size_t)(slot + half * 32 + ii) * DHz + j];
    }
    __syncthreads();

    float* myop = op + half * 4096;
    for (int t = 0; t < CL; t++) {
        float vj = v_s[t * 64 + j];
        const float4* rp = (const float4*)&r_s[t * 64 + half * 32];
        const float4* kp = (const float4*)&k_s[t * 64 + half * 32];
        const float4* ep = (const float4*)&e_s[t * 64 + half * 32];
        float o0 = 0.f, o1 = 0.f, o2 = 0.f, o3 = 0.f;
        #pragma unroll
        for (int q = 0; q < 8; q++) {
            float4 rv = rp[q], kv = kp[q], ev = ep[q];
            o0 += rv.x * s[q * 4 + 0]; s[q * 4 + 0] = ev.x * s[q * 4 + 0] + kv.x * vj;
            o1 += rv.y * s[q * 4 + 1]; s[q * 4 + 1] = ev.y * s[q * 4 + 1] + kv.y * vj;
            o2 += rv.z * s[q * 4 + 2]; s[q * 4 + 2] = ev.z * s[q * 4 + 2] + kv.z * vj;
            o3 += rv.w * s[q * 4 + 3]; s[q * 4 + 3] = ev.w * s[q * 4 + 3] + kv.w * vj;
        }
        myop[t * 64 + j] = ((o0 + o1) + (o2 + o3));
    }
    __syncthreads();

    float* __restrict__ go = g_buf[8];
    #pragma unroll
    for (int it = 0; it < 32; it++) {
        int f  = it * 128 + tid;
        int t  = f >> 6;
        int jj = f & 63;
        float o = op[f] + op[4096 + f] + bs_s[t] * v_s[f];
        go[base0 + t * Dz + jj] = o;
    }
}

// ---------------------------------------------------------------------------
// GroupNorm + r-multiply; outputs tf32-rounded (feeds final GEMM only)
// ---------------------------------------------------------------------------
__global__ void __launch_bounds__(256) gnorm_kernel(const float* __restrict__ ln_w,
                                                    const float* __restrict__ ln_b)
{
    int warp = (blockIdx.x * blockDim.x + threadIdx.x) >> 5;
    int lane = threadIdx.x & 31;
    if (warp >= Bz * Tz * Hz) return;

    int base = warp * 64;
    float a0 = g_buf[8][base + lane];
    float a1 = g_buf[8][base + 32 + lane];

    float sum = a0 + a1;
    float sq  = a0 * a0 + a1 * a1;
    #pragma unroll
    for (int off = 16; off > 0; off >>= 1) {
        sum += __shfl_xor_sync(0xffffffffu, sum, off);
        sq  += __shfl_xor_sync(0xffffffffu, sq,  off);
    }
    float mean = sum * (1.f / 64.f);
    float var  = sq * (1.f / 64.f) - mean * mean;
    float rs   = rsqrtf(var + 1e-5f);

    float r0 = g_buf[4][base + lane];
    float r1 = g_buf[4][base + 32 + lane];
    g_buf[8][base + lane] =
        to_tf32(((a0 - mean) * rs * ln_w[lane] + ln_b[lane]) * r0);
    g_buf[8][base + 32 + lane] =
        to_tf32(((a1 - mean) * rs * ln_w[lane + 32] + ln_b[lane + 32]) * r1);
}

// ---------------------------------------------------------------------------
extern "C" void kernel_launch(void* const* d_in, const int* in_sizes, int n_in,
                              void* d_out, int out_size)
{
    const float* x    = (const float*)d_in[0];
    const float* W_r  = (const float*)d_in[1];
    const float* W_k  = (const float*)d_in[2];
    const float* W_v  = (const float*)d_in[3];
    const float* W_w  = (const float*)d_in[4];
    const float* W_o  = (const float*)d_in[5];
    const float* u    = (const float*)d_in[6];
    const float* tm_r = (const float*)d_in[7];
    const float* tm_k = (const float*)d_in[8];
    const float* tm_v = (const float*)d_in[9];
    const float* tm_w = (const float*)d_in[10];
    const float* ln_w = (const float*)d_in[11];
    const float* ln_b = (const float*)d_in[12];
    float* out = (float*)d_out;

    cudaFuncSetAttribute(scanA_kernel,
        cudaFuncAttributeMaxDynamicSharedMemorySize, 12288 * 4);
    cudaFuncSetAttribute(scanC_kernel,
        cudaFuncAttributeMaxDynamicSharedMemorySize, 24640 * 4);
    cudaFuncSetAttribute(proj_gemm,
        cudaFuncAttributeMaxDynamicSharedMemorySize, GSMB);
    cudaFuncSetAttribute(out_gemm,
        cudaFuncAttributeMaxDynamicSharedMemorySize, GSMB);

    roundw_kernel<<<5120, 256>>>(
        (const float4*)W_r, (const float4*)W_k, (const float4*)W_v,
        (const float4*)W_w, (const float4*)W_o);

    mix_kernel<<<(MD / 4) / 256, 256>>>(
        (const float4*)x, (const float4*)tm_r, (const float4*)tm_k,
        (const float4*)tm_v, (const float4*)tm_w);

    proj_gemm<<<dim3(Nz / 128, Mz / 128, 4), 128, GSMB>>>();

    bonus_kernel<<<(Bz * Tz * Hz) / 8, 256>>>(u);

    scanA_kernel<<<dim3(NC - 1, NBH), 128, 12288 * 4>>>();
    scanB_kernel<<<NBH, 128>>>();
    scanC_kernel<<<dim3(NC, NBH), 128, 24640 * 4>>>();

    gnorm_kernel<<<(Bz * Tz * Hz) / 8, 256>>>(ln_w, ln_b);

    out_gemm<<<dim3(Nz / 128, Mz / 128), 128, GSMB>>>(out);
}

// round 9
// speedup vs baseline: 1.5307x; 1.1313x over previous
#include <cuda_runtime.h>
#include <cstdint>

#define Bz 4
#define Tz 1024
#define Dz 1024
#define Hz 16
#define DHz 64
#define Mz (Bz*Tz)        // 4096
#define Kz Dz
#define Nz Dz
#define MD (Mz*Dz)        // 4,194,304
#define NBH (Bz*Hz)       // 64
#define CL 64             // chunk length
#define NC (Tz/CL)        // 16 chunks

// 0..3 = xr,xk,xv,xw (tf32, k-permuted) ; 4=r ; 5=k ; 6=v ; 7=exp(w) (normal)
// 8=o (normal after scanC, k-permuted tf32 after gnorm)
__device__ float g_buf[9][MD];
__device__ float g_wr[5 * Dz * Dz];               // tf32 k-permuted weights
__device__ float g_state[NBH * NC * DHz * DHz];   // chunk states
__device__ float g_wprod[NBH * NC * DHz];         // per-chunk decay products
__device__ float g_bsum[Bz * Tz * Hz];            // bonus coefficients

__device__ __forceinline__ float to_tf32(float x)
{
    uint32_t d;
    asm("cvt.rna.tf32.f32 %0, %1;" : "=r"(d) : "f"(x));
    return __uint_as_float(d);
}
__device__ __forceinline__ uint32_t smem_to_u32(const void* p) {
    uint32_t a;
    asm("{ .reg .u64 t; cvta.to.shared.u64 t, %1; cvt.u32.u64 %0, t; }"
        : "=r"(a) : "l"(p));
    return a;
}
__device__ __forceinline__ void cp16(uint32_t dst, const void* src) {
    asm volatile("cp.async.cg.shared.global [%0], [%1], 16;"
                 :: "r"(dst), "l"(src));
}
__device__ __forceinline__ void cp_commit() {
    asm volatile("cp.async.commit_group;" ::: "memory");
}
__device__ __forceinline__ void mma_tf32(float c[4], const uint32_t a[4],
                                         const uint32_t b[2])
{
    asm volatile(
        "mma.sync.aligned.m16n8k8.row.col.f32.tf32.tf32.f32 "
        "{%0,%1,%2,%3}, {%4,%5,%6,%7}, {%8,%9}, {%0,%1,%2,%3};"
        : "+f"(c[0]), "+f"(c[1]), "+f"(c[2]), "+f"(c[3])
        : "r"(a[0]), "r"(a[1]), "r"(a[2]), "r"(a[3]),
          "r"(b[0]), "r"(b[1]));
}

// permute helper: 8 floats (a=k0..3, b=k4..7) -> [k0,k4,k1,k5] and [k2,k6,k3,k7]
__device__ __forceinline__ void perm_pair(const float4& a, const float4& b,
                                          float4& o0, float4& o1)
{
    o0 = make_float4(a.x, b.x, a.y, b.y);
    o1 = make_float4(a.z, b.z, a.w, b.w);
}

// ---------------------------------------------------------------------------
// round 5 weight matrices to tf32, k-permuted, into g_wr
// one thread per 8-float group: 5*1M/8 = 655360 threads
// ---------------------------------------------------------------------------
__global__ void __launch_bounds__(256) roundw_kernel(
    const float4* __restrict__ a, const float4* __restrict__ b,
    const float4* __restrict__ c, const float4* __restrict__ d,
    const float4* __restrict__ e)
{
    int idx = blockIdx.x * 256 + threadIdx.x;      // 0..655359
    int which = idx >> 17;                         // /131072
    int off = idx & 131071;
    const float4* src = which == 0 ? a : which == 1 ? b : which == 2 ? c
                       : which == 3 ? d : e;
    float4 v0 = src[2 * off], v1 = src[2 * off + 1];
    v0.x = to_tf32(v0.x); v0.y = to_tf32(v0.y); v0.z = to_tf32(v0.z); v0.w = to_tf32(v0.w);
    v1.x = to_tf32(v1.x); v1.y = to_tf32(v1.y); v1.z = to_tf32(v1.z); v1.w = to_tf32(v1.w);
    float4 o0, o1;
    perm_pair(v0, v1, o0, o1);
    float4* dst = reinterpret_cast<float4*>(g_wr) + (size_t)which * 262144;
    dst[2 * off] = o0;
    dst[2 * off + 1] = o1;
}

// ---------------------------------------------------------------------------
// token-shift mix, tf32-rounded + k-permuted. one thread per 8-float group.
// ---------------------------------------------------------------------------
__global__ void __launch_bounds__(256) mix_kernel(
    const float4* __restrict__ x,
    const float4* __restrict__ tmr, const float4* __restrict__ tmk,
    const float4* __restrict__ tmv, const float4* __restrict__ tmw)
{
    int idx = blockIdx.x * 256 + threadIdx.x;   // over MD/8 = 524288
    int m  = idx >> 7;                          // 128 groups per row
    int gg = idx & 127;
    int t  = m & (Tz - 1);

    float4 x0 = x[(m << 8) + 2 * gg];
    float4 x1 = x[(m << 8) + 2 * gg + 1];
    float4 p0 = make_float4(0.f, 0.f, 0.f, 0.f), p1 = p0;
    if (t != 0) {
        p0 = x[((m - 1) << 8) + 2 * gg];
        p1 = x[((m - 1) << 8) + 2 * gg + 1];
    }

    #define DO_MIX(TMV, DSTI)                                               \
    {                                                                       \
        float4 w0 = TMV[2 * gg], w1 = TMV[2 * gg + 1];                      \
        float4 a, b;                                                        \
        a.x = to_tf32(w0.x * x0.x + (1.f - w0.x) * p0.x);                   \
        a.y = to_tf32(w0.y * x0.y + (1.f - w0.y) * p0.y);                   \
        a.z = to_tf32(w0.z * x0.z + (1.f - w0.z) * p0.z);                   \
        a.w = to_tf32(w0.w * x0.w + (1.f - w0.w) * p0.w);                   \
        b.x = to_tf32(w1.x * x1.x + (1.f - w1.x) * p1.x);                   \
        b.y = to_tf32(w1.y * x1.y + (1.f - w1.y) * p1.y);                   \
        b.z = to_tf32(w1.z * x1.z + (1.f - w1.z) * p1.z);                   \
        b.w = to_tf32(w1.w * x1.w + (1.f - w1.w) * p1.w);                   \
        float4 o0, o1;                                                      \
        perm_pair(a, b, o0, o1);                                            \
        reinterpret_cast<float4*>(g_buf[DSTI])[2 * idx]     = o0;           \
        reinterpret_cast<float4*>(g_buf[DSTI])[2 * idx + 1] = o1;           \
    }
    DO_MIX(tmr, 0)
    DO_MIX(tmk, 1)
    DO_MIX(tmv, 2)
    DO_MIX(tmw, 3)
    #undef DO_MIX
}

// ---------------------------------------------------------------------------
// tf32 mma.sync GEMM on k-permuted operands.
// CTA tile 128x128, BK=32, 4 warps (2m x 2n), warp tile 64x64.
// 3-stage cp.async pipeline, swizzled pad-free smem (128B rows),
// fragment loads as LDS.64 (one per (k,k+4) pair). 2 CTAs/SM.
// ---------------------------------------------------------------------------
#define TB 4096                               // floats per tile buffer
#define GSMB (3 * 2 * TB * 4)                 // 98304 bytes

__device__ __forceinline__ void gemm_body(
    const float* __restrict__ A,
    const float* __restrict__ W,
    float* __restrict__ C, int epi)
{
    extern __shared__ __align__(16) float sm[];
    float* As = sm;                  // [3][TB]
    float* Bs = sm + 3 * TB;
    uint32_t a32 = smem_to_u32(As);
    uint32_t b32 = smem_to_u32(Bs);

    int tid  = threadIdx.x;          // 0..127
    int lane = tid & 31;
    int wid  = tid >> 5;
    int bm = blockIdx.y * 128;
    int bn = blockIdx.x * 128;

    int wm = (wid >> 1) * 64;
    int wn = (wid & 1) * 64;
    int frow = lane >> 2;
    int fk   = lane & 3;

    float acc[4][8][4];
    #pragma unroll
    for (int i = 0; i < 4; i++)
        #pragma unroll
        for (int j = 0; j < 8; j++)
            #pragma unroll
            for (int r = 0; r < 4; r++) acc[i][j][r] = 0.f;

    // stage: 128 rows x 8 granules(16B) per matrix; slot swizzle (g+2(r&3))&7
    #define GSTAGE(CC, BUF)                                                  \
    {                                                                        \
        const char* ap = (const char*)(A + (size_t)bm * Kz + (CC) * 32);     \
        const char* bp = (const char*)(W + (size_t)bn * Kz + (CC) * 32);     \
        _Pragma("unroll")                                                    \
        for (int i = 0; i < 8; i++) {                                        \
            int lin = i * 128 + tid;                                         \
            int r = lin >> 3;                                                \
            int g = lin & 7;                                                 \
            int slot = (g + 2 * (r & 3)) & 7;                                \
            cp16(a32 + (BUF) * (TB * 4) + r * 128 + slot * 16,               \
                 ap + (size_t)r * (Kz * 4) + g * 16);                        \
            cp16(b32 + (BUF) * (TB * 4) + r * 128 + slot * 16,               \
                 bp + (size_t)r * (Kz * 4) + g * 16);                        \
        }                                                                    \
    }

    GSTAGE(0, 0) cp_commit();
    GSTAGE(1, 1) cp_commit();

    const int NIT = Kz >> 5;         // 32
    int buf = 0;
    for (int c = 0; c < NIT; c++) {
        asm volatile("cp.async.wait_group 1;" ::: "memory");
        __syncthreads();
        if (c + 2 < NIT) {
            int nb = (c + 2) % 3;
            if (nb == 0)      { GSTAGE(c + 2, 0) }
            else if (nb == 1) { GSTAGE(c + 2, 1) }
            else              { GSTAGE(c + 2, 2) }
        }
        cp_commit();

        const float* a_s = As + buf * TB;
        const float* b_s = Bs + buf * TB;
        #pragma unroll
        for (int ks = 0; ks < 4; ks++) {
            uint32_t afr[4][4], bfr[8][2];
            int slot = (2 * ks + (fk >> 1) + 2 * (frow & 3)) & 7;
            int fo = slot * 4 + (fk & 1) * 2;   // float offset within 32f row
            #pragma unroll
            for (int mt = 0; mt < 4; mt++) {
                int rr = wm + mt * 16 + frow;
                float2 u = *(const float2*)&a_s[rr * 32 + fo];
                float2 v = *(const float2*)&a_s[(rr + 8) * 32 + fo];
                afr[mt][0] = __float_as_uint(u.x);
                afr[mt][1] = __float_as_uint(v.x);
                afr[mt][2] = __float_as_uint(u.y);
                afr[mt][3] = __float_as_uint(v.y);
            }
            #pragma unroll
            for (int nt = 0; nt < 8; nt++) {
                int rn = wn + nt * 8 + frow;
                float2 w2 = *(const float2*)&b_s[rn * 32 + fo];
                bfr[nt][0] = __float_as_uint(w2.x);
                bfr[nt][1] = __float_as_uint(w2.y);
            }
            #pragma unroll
            for (int mt = 0; mt < 4; mt++)
                #pragma unroll
                for (int nt = 0; nt < 8; nt++)
                    mma_tf32(acc[mt][nt], afr[mt], bfr[nt]);
        }
        buf = (buf + 1) == 3 ? 0 : buf + 1;
    }
    #undef GSTAGE

    #pragma unroll
    for (int mt = 0; mt < 4; mt++) {
        int row = bm + wm + mt * 16 + frow;
        #pragma unroll
        for (int nt = 0; nt < 8; nt++) {
            int col = bn + wn + nt * 8 + fk * 2;
            float vv[4];
            #pragma unroll
            for (int r = 0; r < 4; r++) {
                float v = acc[mt][nt][r];
                if (epi == 1)      v = 1.f / (1.f + __expf(-v));
                else if (epi == 2) v = 0.999900004999833f / (1.f + __expf(-v));
                vv[r] = v;
            }
            *(float2*)&C[(size_t)row * Nz + col]       = make_float2(vv[0], vv[1]);
            *(float2*)&C[(size_t)(row + 8) * Nz + col] = make_float2(vv[2], vv[3]);
        }
    }
}

__global__ void __launch_bounds__(128, 2) proj_gemm()
{
    int which = blockIdx.z;
    int epi = (which == 0) ? 1 : (which == 3) ? 2 : 0;
    gemm_body(g_buf[which], g_wr + (size_t)which * (Dz * Dz),
              g_buf[4 + which], epi);
}

__global__ void __launch_bounds__(128, 2) out_gemm(float* __restrict__ out)
{
    gemm_body(g_buf[8], g_wr + (size_t)4 * (Dz * Dz), out, 0);
}

// ---------------------------------------------------------------------------
// bonus coefficients: g_bsum[b,t,h] = sum_i r[i] * exp(u[i]+k[i])
// ---------------------------------------------------------------------------
__global__ void __launch_bounds__(256) bonus_kernel(const float* __restrict__ u)
{
    int warp = (blockIdx.x * blockDim.x + threadIdx.x) >> 5;
    int lane = threadIdx.x & 31;
    if (warp >= Bz * Tz * Hz) return;
    int bt = warp / Hz;
    int h  = warp - bt * Hz;

    int base = bt * Dz + h * 64;
    float r0 = g_buf[4][base + lane];
    float r1 = g_buf[4][base + 32 + lane];
    float k0 = g_buf[5][base + lane];
    float k1 = g_buf[5][base + 32 + lane];
    float u0 = u[h * 64 + lane];
    float u1 = u[h * 64 + 32 + lane];

    float term = r0 * __expf(u0 + k0) + r1 * __expf(u1 + k1);
    #pragma unroll
    for (int off = 16; off > 0; off >>= 1)
        term += __shfl_xor_sync(0xffffffffu, term, off);
    if (lane == 0) g_bsum[warp] = term;
}

// ---------------------------------------------------------------------------
// Pass A: chunk-local scan, zero init. grid (NC-1, NBH), 128 threads.
// ---------------------------------------------------------------------------
__global__ void __launch_bounds__(128) scanA_kernel()
{
    extern __shared__ __align__(16) float sm[];
    float* k_s = sm;
    float* e_s = sm + 4096;
    float* v_s = sm + 8192;

    int tid  = threadIdx.x;
    int j    = tid & 63;
    int half = tid >> 6;
    int c  = blockIdx.x;
    int bh = blockIdx.y;
    int b = bh >> 4, h = bh & 15;

    int base0 = (b * Tz + c * CL) * Dz + h * 64;

    #pragma unroll
    for (int it = 0; it < 8; it++) {
        int f  = it * 128 + tid;
        int t  = f >> 4;
        int i4 = (f & 15) << 2;
        int ga = base0 + t * Dz + i4;
        int sa = t * 64 + i4;
        *(float4*)&k_s[sa] = *(const float4*)&g_buf[5][ga];
        *(float4*)&e_s[sa] = *(const float4*)&g_buf[7][ga];
        *(float4*)&v_s[sa] = *(const float4*)&g_buf[6][ga];
    }
    __syncthreads();

    float s[32];
    #pragma unroll
    for (int i = 0; i < 32; i++) s[i] = 0.f;

    for (int t = 0; t < CL; t++) {
        float vj = v_s[t * 64 + j];
        const float4* kp = (const float4*)&k_s[t * 64 + half * 32];
        const float4* ep = (const float4*)&e_s[t * 64 + half * 32];
        #pragma unroll
        for (int q = 0; q < 8; q++) {
            float4 kv = kp[q], ev = ep[q];
            s[q * 4 + 0] = ev.x * s[q * 4 + 0] + kv.x * vj;
            s[q * 4 + 1] = ev.y * s[q * 4 + 1] + kv.y * vj;
            s[q * 4 + 2] = ev.z * s[q * 4 + 2] + kv.z * vj;
            s[q * 4 + 3] = ev.w * s[q * 4 + 3] + kv.w * vj;
        }
    }

    int slot = (bh * NC + c) * DHz;
    #pragma unroll 8
    for (int ii = 0; ii < 32; ii++)
        g_state[(size_t)(slot + half * 32 + ii) * DHz + j] = s[ii];

    if (half == 0) {
        float w0 = 1.f, w1 = 1.f, w2 = 1.f, w3 = 1.f;
        #pragma unroll
        for (int t = 0; t < CL; t += 4) {
            w0 *= e_s[(t + 0) * 64 + j];
            w1 *= e_s[(t + 1) * 64 + j];
            w2 *= e_s[(t + 2) * 64 + j];
            w3 *= e_s[(t + 3) * 64 + j];
        }
        g_wprod[slot + j] = (w0 * w1) * (w2 * w3);
    }
}

// ---------------------------------------------------------------------------
// Pass B: sequential prefix over chunks. grid NBH, 256 threads (i quarter-split)
// ---------------------------------------------------------------------------
__global__ void __launch_bounds__(256) scanB_kernel()
{
    __shared__ float s_w[64];
    int tid = threadIdx.x;
    int j   = tid & 63;
    int q   = tid >> 6;        // 0..3
    int bh = blockIdx.x;

    float R[16];
    #pragma unroll
    for (int i = 0; i < 16; i++) R[i] = 0.f;

    for (int c = 0; c < NC; c++) {
        int slot = (bh * NC + c) * DHz;
        if (c < NC - 1) {
            if (tid < 64) s_w[tid] = g_wprod[slot + tid];
            __syncthreads();
            #pragma unroll 8
            for (int ii = 0; ii < 16; ii++) {
                int i = q * 16 + ii;
                size_t a = (size_t)(slot + i) * DHz + j;
                float local = g_state[a];
                g_state[a] = R[ii];
                R[ii] = s_w[i] * R[ii] + local;
            }
            __syncthreads();
        } else {
            #pragma unroll 8
            for (int ii = 0; ii < 16; ii++)
                g_state[(size_t)(slot + q * 16 + ii) * DHz + j] = R[ii];
        }
    }
}

// ---------------------------------------------------------------------------
// Pass C: outputs. grid (NC, NBH), 128 threads, no per-step barriers.
// ---------------------------------------------------------------------------
__global__ void __launch_bounds__(128) scanC_kernel()
{
    extern __shared__ __align__(16) float sm[];
    float* k_s = sm;
    float* e_s = sm + 4096;
    float* v_s = sm + 8192;
    float* r_s = sm + 12288;
    float* op  = sm + 16384;
    float* bs_s = sm + 24576;

    int tid  = threadIdx.x;
    int j    = tid & 63;
    int half = tid >> 6;
    int c  = blockIdx.x;
    int bh = blockIdx.y;
    int b = bh >> 4, h = bh & 15;

    int base0 = (b * Tz + c * CL) * Dz + h * 64;
    int bbase = (b * Tz + c * CL) * Hz + h;

    #pragma unroll
    for (int it = 0; it < 8; it++) {
        int f  = it * 128 + tid;
        int t  = f >> 4;
        int i4 = (f & 15) << 2;
        int ga = base0 + t * Dz + i4;
        int sa = t * 64 + i4;
        *(float4*)&k_s[sa] = *(const float4*)&g_buf[5][ga];
        *(float4*)&e_s[sa] = *(const float4*)&g_buf[7][ga];
        *(float4*)&v_s[sa] = *(const float4*)&g_buf[6][ga];
        *(float4*)&r_s[sa] = *(const float4*)&g_buf[4][ga];
    }
    if (tid < 64) bs_s[tid] = g_bsum[bbase + tid * Hz];

    float s[32];
    {
        int slot = (bh * NC + c) * DHz;
        #pragma unroll 8
        for (int ii = 0; ii < 32; ii++)
            s[ii] = g_state[(size_t)(slot + half * 32 + ii) * DHz + j];
    }
    __syncthreads();

    float* myop = op + half * 4096;
    for (int t = 0; t < CL; t++) {
        float vj = v_s[t * 64 + j];
        const float4* rp = (const float4*)&r_s[t * 64 + half * 32];
        const float4* kp = (const float4*)&k_s[t * 64 + half * 32];
        const float4* ep = (const float4*)&e_s[t * 64 + half * 32];
        float o0 = 0.f, o1 = 0.f, o2 = 0.f, o3 = 0.f;
        #pragma unroll
        for (int q = 0; q < 8; q++) {
            float4 rv = rp[q], kv = kp[q], ev = ep[q];
            o0 += rv.x * s[q * 4 + 0]; s[q * 4 + 0] = ev.x * s[q * 4 + 0] + kv.x * vj;
            o1 += rv.y * s[q * 4 + 1]; s[q * 4 + 1] = ev.y * s[q * 4 + 1] + kv.y * vj;
            o2 += rv.z * s[q * 4 + 2]; s[q * 4 + 2] = ev.z * s[q * 4 + 2] + kv.z * vj;
            o3 += rv.w * s[q * 4 + 3]; s[q * 4 + 3] = ev.w * s[q * 4 + 3] + kv.w * vj;
        }
        myop[t * 64 + j] = ((o0 + o1) + (o2 + o3));
    }
    __syncthreads();

    float* __restrict__ go = g_buf[8];
    #pragma unroll
    for (int it = 0; it < 32; it++) {
        int f  = it * 128 + tid;
        int t  = f >> 6;
        int jj = f & 63;
        float o = op[f] + op[4096 + f] + bs_s[t] * v_s[f];
        go[base0 + t * Dz + jj] = o;
    }
}

// ---------------------------------------------------------------------------
// GroupNorm + r-multiply; writes tf32-rounded k-PERMUTED (feeds out_gemm only)
// lane handles orig indices a=(lane>>2)*8+(lane&3) and a+4; writes float2 at
// permuted position (lane>>2)*8 + 2*(lane&3).
// ---------------------------------------------------------------------------
__global__ void __launch_bounds__(256) gnorm_kernel(const float* __restrict__ ln_w,
                                                    const float* __restrict__ ln_b)
{
    int warp = (blockIdx.x * blockDim.x + threadIdx.x) >> 5;
    int lane = threadIdx.x & 31;
    if (warp >= Bz * Tz * Hz) return;

    int g = lane >> 2;
    int w = lane & 3;
    int a  = g * 8 + w;
    int a2 = a + 4;
    int base = warp * 64;

    float o0 = g_buf[8][base + a];
    float o1 = g_buf[8][base + a2];

    float sum = o0 + o1;
    float sq  = o0 * o0 + o1 * o1;
    #pragma unroll
    for (int off = 16; off > 0; off >>= 1) {
        sum += __shfl_xor_sync(0xffffffffu, sum, off);
        sq  += __shfl_xor_sync(0xffffffffu, sq,  off);
    }
    float mean = sum * (1.f / 64.f);
    float var  = sq * (1.f / 64.f) - mean * mean;
    float rs   = rsqrtf(var + 1e-5f);

    float r0 = g_buf[4][base + a];
    float r1 = g_buf[4][base + a2];
    float n0 = to_tf32(((o0 - mean) * rs * ln_w[a]  + ln_b[a])  * r0);
    float n1 = to_tf32(((o1 - mean) * rs * ln_w[a2] + ln_b[a2]) * r1);
    *(float2*)&g_buf[8][base + g * 8 + 2 * w] = make_float2(n0, n1);
}

// ---------------------------------------------------------------------------
extern "C" void kernel_launch(void* const* d_in, const int* in_sizes, int n_in,
                              void* d_out, int out_size)
{
    const float* x    = (const float*)d_in[0];
    const float* W_r  = (const float*)d_in[1];
    const float* W_k  = (const float*)d_in[2];
    const float* W_v  = (const float*)d_in[3];
    const float* W_w  = (const float*)d_in[4];
    const float* W_o  = (const float*)d_in[5];
    const float* u    = (const float*)d_in[6];
    const float* tm_r = (const float*)d_in[7];
    const float* tm_k = (const float*)d_in[8];
    const float* tm_v = (const float*)d_in[9];
    const float* tm_w = (const float*)d_in[10];
    const float* ln_w = (const float*)d_in[11];
    const float* ln_b = (const float*)d_in[12];
    float* out = (float*)d_out;

    cudaFuncSetAttribute(scanA_kernel,
        cudaFuncAttributeMaxDynamicSharedMemorySize, 12288 * 4);
    cudaFuncSetAttribute(scanC_kernel,
        cudaFuncAttributeMaxDynamicSharedMemorySize, 24640 * 4);
    cudaFuncSetAttribute(proj_gemm,
        cudaFuncAttributeMaxDynamicSharedMemorySize, GSMB);
    cudaFuncSetAttribute(out_gemm,
        cudaFuncAttributeMaxDynamicSharedMemorySize, GSMB);

    roundw_kernel<<<2560, 256>>>(
        (const float4*)W_r, (const float4*)W_k, (const float4*)W_v,
        (const float4*)W_w, (const float4*)W_o);

    mix_kernel<<<2048, 256>>>(
        (const float4*)x, (const float4*)tm_r, (const float4*)tm_k,
        (const float4*)tm_v, (const float4*)tm_w);

    proj_gemm<<<dim3(Nz / 128, Mz / 128, 4), 128, GSMB>>>();

    bonus_kernel<<<(Bz * Tz * Hz) / 8, 256>>>(u);

    scanA_kernel<<<dim3(NC - 1, NBH), 128, 12288 * 4>>>();
    scanB_kernel<<<NBH, 256>>>();
    scanC_kernel<<<dim3(NC, NBH), 128, 24640 * 4>>>();

    gnorm_kernel<<<(Bz * Tz * Hz) / 8, 256>>>(ln_w, ln_b);

    out_gemm<<<dim3(Nz / 128, Mz / 128), 128, GSMB>>>(out);
}